// round 1
// baseline (speedup 1.0000x reference)
#include <cuda_runtime.h>

// Problem constants (fixed shapes per reference)
#define N_ROWS   2048
#define DDIM     256
#define T_TRACKS 256
#define QN       64
#define NY       (T_TRACKS * QN)      // 16384 y-columns
#define NTOT     (NY + N_ROWS)        // 18432 total columns
#define BM       64
#define BN       64
#define KC       64
#define TILES_PER_CHUNK 8             // 512 cols per block; 16384 % 512 == 0
#define INV_TEMP (1.0f / 0.3f)

// Per-row accumulators (scratch; no device allocation allowed)
__device__ float g_rxy_tot[N_ROWS];
__device__ float g_rxy_pos[N_ROWS];
__device__ float g_rxx_tot[N_ROWS];
__device__ float g_rxx_pos[N_ROWS];
__device__ float g_diag[N_ROWS];

__global__ void init_kernel() {
    int i = blockIdx.x * blockDim.x + threadIdx.x;
    if (i < N_ROWS) {
        g_rxy_tot[i] = 0.f;
        g_rxy_pos[i] = 0.f;
        g_rxx_tot[i] = 0.f;
        g_rxx_pos[i] = 0.f;
    }
}

// ---- packed fp32x2 helpers (Blackwell 2-wide fp32 pipe) ----
__device__ __forceinline__ unsigned long long pack_dup(float v) {
    unsigned long long r;
    asm("mov.b64 %0, {%1, %1};" : "=l"(r) : "f"(v));
    return r;
}
__device__ __forceinline__ void fma2(unsigned long long& d,
                                     unsigned long long a,
                                     unsigned long long b) {
    asm("fma.rn.f32x2 %0, %1, %2, %0;" : "+l"(d) : "l"(a), "l"(b));
}
__device__ __forceinline__ float2 unpack2(unsigned long long v) {
    float2 r;
    asm("mov.b64 {%0, %1}, %2;" : "=f"(r.x), "=f"(r.y) : "l"(v));
    return r;
}

// Fused exp-GEMM + masked row reductions.
// Columns [0, NY): z = yf (labels j & 255).  Columns [NY, NTOT): z = x (labels tid[j-NY]).
__global__ __launch_bounds__(256) void sim_kernel(const float* __restrict__ x,
                                                  const int*   __restrict__ tid,
                                                  const float* __restrict__ y) {
    __shared__ __align__(16) float xs[KC][BM];   // K-major x tile
    __shared__ __align__(16) float zs[KC][BN];   // K-major z tile

    const int t  = threadIdx.x;
    const int ty = t >> 4;       // 0..15 -> row group
    const int tx = t & 15;       // 0..15 -> col group
    const int r0 = ty * 4;

    const int row_base   = blockIdx.x * BM;
    const int chunk_base = blockIdx.y * (BN * TILES_PER_CHUNK);
    const bool is_xx     = (chunk_base >= NY);

    int myTid[4];
#pragma unroll
    for (int rr = 0; rr < 4; rr++) myTid[rr] = tid[row_base + r0 + rr];

    float tot[4] = {0.f, 0.f, 0.f, 0.f};
    float pos[4] = {0.f, 0.f, 0.f, 0.f};

    // smem fill mapping: 256 threads, each loads one row x 4 float4 chunks
    const int lrow = t >> 2;     // 0..63
    const int lq   = t & 3;      // 0..3

    const float* xptr = x + (size_t)row_base * DDIM;

    for (int tile = 0; tile < TILES_PER_CHUNK; tile++) {
        const int col_base = chunk_base + tile * BN;
        const float* zptr = is_xx ? (x + (size_t)(col_base - NY) * DDIM)
                                  : (y + (size_t)col_base * DDIM);

        unsigned long long acc2[4][2];
#pragma unroll
        for (int a = 0; a < 4; a++) { acc2[a][0] = 0ull; acc2[a][1] = 0ull; }

        for (int k0 = 0; k0 < DDIM; k0 += KC) {
            __syncthreads();
#pragma unroll
            for (int i = 0; i < 4; i++) {
                const int kk = (lq * 4 + i) * 4;  // multiples of 4 in [0,64)
                float4 v = *(const float4*)(xptr + (size_t)lrow * DDIM + k0 + kk);
                xs[kk + 0][lrow] = v.x; xs[kk + 1][lrow] = v.y;
                xs[kk + 2][lrow] = v.z; xs[kk + 3][lrow] = v.w;
                float4 w = *(const float4*)(zptr + (size_t)lrow * DDIM + k0 + kk);
                zs[kk + 0][lrow] = w.x; zs[kk + 1][lrow] = w.y;
                zs[kk + 2][lrow] = w.z; zs[kk + 3][lrow] = w.w;
            }
            __syncthreads();

#pragma unroll
            for (int k = 0; k < KC; k++) {
                const float4 av = *(const float4*)&xs[k][r0];
                const ulonglong2 bb = *(const ulonglong2*)&zs[k][tx * 4];
                const unsigned long long a0 = pack_dup(av.x);
                const unsigned long long a1 = pack_dup(av.y);
                const unsigned long long a2 = pack_dup(av.z);
                const unsigned long long a3 = pack_dup(av.w);
                fma2(acc2[0][0], a0, bb.x); fma2(acc2[0][1], a0, bb.y);
                fma2(acc2[1][0], a1, bb.x); fma2(acc2[1][1], a1, bb.y);
                fma2(acc2[2][0], a2, bb.x); fma2(acc2[2][1], a2, bb.y);
                fma2(acc2[3][0], a3, bb.x); fma2(acc2[3][1], a3, bb.y);
            }
        }

        // epilogue: exp + masked accumulation
        int lab[4];
#pragma unroll
        for (int cc = 0; cc < 4; cc++) {
            const int gcol = col_base + tx * 4 + cc;
            lab[cc] = is_xx ? tid[gcol - NY] : (gcol & (T_TRACKS - 1));
        }
#pragma unroll
        for (int rr = 0; rr < 4; rr++) {
            const int grow = row_base + r0 + rr;
            float ev[4];
            const float2 p0 = unpack2(acc2[rr][0]);
            const float2 p1 = unpack2(acc2[rr][1]);
            ev[0] = __expf(p0.x * INV_TEMP);
            ev[1] = __expf(p0.y * INV_TEMP);
            ev[2] = __expf(p1.x * INV_TEMP);
            ev[3] = __expf(p1.y * INV_TEMP);
#pragma unroll
            for (int cc = 0; cc < 4; cc++) {
                tot[rr] += ev[cc];
                if (lab[cc] == myTid[rr]) pos[rr] += ev[cc];
                if (is_xx) {
                    const int gcol = col_base + tx * 4 + cc;
                    if ((gcol - NY) == grow) g_diag[grow] = ev[cc];
                }
            }
        }
    }

    // reduce over tx (16-lane groups within each warp), then atomics
#pragma unroll
    for (int rr = 0; rr < 4; rr++) {
        float tv = tot[rr], pv = pos[rr];
#pragma unroll
        for (int off = 1; off < 16; off <<= 1) {
            tv += __shfl_xor_sync(0xffffffffu, tv, off);
            pv += __shfl_xor_sync(0xffffffffu, pv, off);
        }
        if (tx == 0) {
            const int grow = row_base + r0 + rr;
            if (is_xx) {
                atomicAdd(&g_rxx_tot[grow], tv);
                atomicAdd(&g_rxx_pos[grow], pv);
            } else {
                atomicAdd(&g_rxy_tot[grow], tv);
                atomicAdd(&g_rxy_pos[grow], pv);
            }
        }
    }
}

// Per-track segment sums + soft-condition loss -> scalar
__global__ void finalize_kernel(const int* __restrict__ tid, float* __restrict__ out) {
    __shared__ float num_s[T_TRACKS];
    __shared__ float den_s[T_TRACKS];
    __shared__ int   cnt_s[T_TRACKS];
    __shared__ float lsum[8];
    __shared__ float psum[8];

    const int t = threadIdx.x;
    num_s[t] = 0.f; den_s[t] = 0.f; cnt_s[t] = 0;
    __syncthreads();

    for (int i = t; i < N_ROWS; i += 256) {
        const int tr = tid[i];
        const float rxyp = g_rxy_pos[i];
        const float rxyt = g_rxy_tot[i];
        const float rxxp = g_rxx_pos[i];   // rxx_pos_full
        const float rxxt = g_rxx_tot[i];
        const float dg   = g_diag[i];
        const float num_i = rxyp + 0.5f * (rxxp - dg);
        const float den_i = (rxyt - rxyp) + (rxxt - rxxp);
        atomicAdd(&num_s[tr], num_i);
        atomicAdd(&den_s[tr], den_i);
        atomicAdd(&cnt_s[tr], 1);
    }
    __syncthreads();

    float loss = 0.f, pres = 0.f;
    if (cnt_s[t] > 0) {
        const float n = num_s[t];
        const float d = den_s[t];
        loss = -logf(n / (d + n));
        pres = 1.f;
    }
#pragma unroll
    for (int off = 16; off; off >>= 1) {
        loss += __shfl_xor_sync(0xffffffffu, loss, off);
        pres += __shfl_xor_sync(0xffffffffu, pres, off);
    }
    if ((t & 31) == 0) { lsum[t >> 5] = loss; psum[t >> 5] = pres; }
    __syncthreads();
    if (t == 0) {
        float L = 0.f, P = 0.f;
#pragma unroll
        for (int w = 0; w < 8; w++) { L += lsum[w]; P += psum[w]; }
        out[0] = L / P;
    }
}

extern "C" void kernel_launch(void* const* d_in, const int* in_sizes, int n_in,
                              void* d_out, int out_size) {
    const float* x   = (const float*)d_in[0];
    const int*   tid = (const int*)d_in[1];
    const float* y   = (const float*)d_in[2];
    float* out = (float*)d_out;

    init_kernel<<<(N_ROWS + 255) / 256, 256>>>();
    dim3 grid(N_ROWS / BM, NTOT / (BN * TILES_PER_CHUNK));  // 32 x 36
    sim_kernel<<<grid, 256>>>(x, tid, y);
    finalize_kernel<<<1, 256>>>(tid, out);
}

// round 2
// speedup vs baseline: 2.9679x; 2.9679x over previous
#include <cuda_runtime.h>

#define N_ROWS   2048
#define DDIM     256
#define T_TRACKS 256
#define QN       64
#define NY       (T_TRACKS * QN)      // 16384 y-columns
#define NTOT     (NY + N_ROWS)        // 18432 total columns
#define BM       128
#define BN       256
#define KC       16
#define SLD      20                   // smem row stride (floats), conflict-free
#define INV_TEMP (1.0f / 0.3f)

// Scratch accumulators (zero-initialized at module load; finalize self-cleans)
__device__ float g_rxy_tot[N_ROWS];
__device__ float g_rxy_pos[N_ROWS];
__device__ float g_rxx_tot[N_ROWS];
__device__ float g_rxx_pos[N_ROWS];
__device__ float g_diag[N_ROWS];

__device__ __forceinline__ unsigned tf32(float f) {
    unsigned r;
    asm("cvt.rna.tf32.f32 %0, %1;" : "=r"(r) : "f"(f));
    return r;
}

__device__ __forceinline__ void mma_tf32(float* c, const unsigned* a, const unsigned* b) {
    asm volatile(
        "mma.sync.aligned.m16n8k8.row.col.f32.tf32.tf32.f32 "
        "{%0,%1,%2,%3}, {%4,%5,%6,%7}, {%8,%9}, {%0,%1,%2,%3};"
        : "+f"(c[0]), "+f"(c[1]), "+f"(c[2]), "+f"(c[3])
        : "r"(a[0]), "r"(a[1]), "r"(a[2]), "r"(a[3]), "r"(b[0]), "r"(b[1]));
}

// Fused TF32 tensor-core exp-GEMM + masked row reductions.
// Cols [0,NY): z = y-flat (label = col & 255).  Cols [NY,NTOT): z = x (label = tid[col-NY]).
__global__ __launch_bounds__(256, 1) void sim_kernel(const float* __restrict__ x,
                                                     const int*   __restrict__ tid,
                                                     const float* __restrict__ y) {
    __shared__ unsigned as[BM * SLD];   // A tile [m][k], tf32 bits
    __shared__ unsigned bs[BN * SLD];   // B tile [n][k], tf32 bits

    const int t    = threadIdx.x;
    const int lane = t & 31;
    const int w    = t >> 5;        // 8 warps
    const int wm   = w >> 2;        // 0..1
    const int wn   = w & 3;         // 0..3
    const int g    = lane >> 2;     // 0..7
    const int tq   = lane & 3;      // 0..3

    const int rowBase = blockIdx.x * BM;
    const int colBase = blockIdx.y * BN;
    const bool is_xx  = (colBase >= NY);
    const float* zptr = is_xx ? (x + (size_t)(colBase - NY) * DDIM)
                              : (y + (size_t)colBase * DDIM);
    const float* xptr = x + (size_t)rowBase * DDIM;

    // loader mapping
    const int arow = t >> 1;                 // 0..127
    const int acol = (t & 1) * 8;            // 0 or 8
    const int brow = t;                      // 0..255

    float4 pa[2], pb[4];
    auto ldg_chunk = [&](int k0) {
        const float* ap = xptr + (size_t)arow * DDIM + k0 + acol;
        pa[0] = *(const float4*)(ap + 0);
        pa[1] = *(const float4*)(ap + 4);
        const float* bp = zptr + (size_t)brow * DDIM + k0;
#pragma unroll
        for (int i = 0; i < 4; i++) pb[i] = *(const float4*)(bp + 4 * i);
    };

    float c[4][8][4];
#pragma unroll
    for (int mt = 0; mt < 4; mt++)
#pragma unroll
        for (int nt = 0; nt < 8; nt++)
#pragma unroll
            for (int q = 0; q < 4; q++) c[mt][nt][q] = 0.f;

    ldg_chunk(0);

    for (int ch = 0; ch < DDIM / KC; ch++) {
        // STS (convert to tf32)
        {
            unsigned* ad = &as[arow * SLD + acol];
            ad[0] = tf32(pa[0].x); ad[1] = tf32(pa[0].y);
            ad[2] = tf32(pa[0].z); ad[3] = tf32(pa[0].w);
            ad[4] = tf32(pa[1].x); ad[5] = tf32(pa[1].y);
            ad[6] = tf32(pa[1].z); ad[7] = tf32(pa[1].w);
            unsigned* bd = &bs[brow * SLD];
#pragma unroll
            for (int i = 0; i < 4; i++) {
                bd[4 * i + 0] = tf32(pb[i].x); bd[4 * i + 1] = tf32(pb[i].y);
                bd[4 * i + 2] = tf32(pb[i].z); bd[4 * i + 3] = tf32(pb[i].w);
            }
        }
        __syncthreads();
        if (ch + 1 < DDIM / KC) ldg_chunk((ch + 1) * KC);

#pragma unroll
        for (int ks = 0; ks < 2; ks++) {
            const int k0 = ks * 8;
            unsigned af[4][4];
#pragma unroll
            for (int mt = 0; mt < 4; mt++) {
                const int rb = (wm * 64 + mt * 16 + g) * SLD + k0;
                af[mt][0] = as[rb + tq];
                af[mt][1] = as[rb + 8 * SLD + tq];
                af[mt][2] = as[rb + tq + 4];
                af[mt][3] = as[rb + 8 * SLD + tq + 4];
            }
            unsigned bf[8][2];
#pragma unroll
            for (int nt = 0; nt < 8; nt++) {
                const int nb = (wn * 64 + nt * 8 + g) * SLD + k0;
                bf[nt][0] = bs[nb + tq];
                bf[nt][1] = bs[nb + tq + 4];
            }
#pragma unroll
            for (int mt = 0; mt < 4; mt++)
#pragma unroll
                for (int nt = 0; nt < 8; nt++) mma_tf32(c[mt][nt], af[mt], bf[nt]);
        }
        __syncthreads();
    }

    // ---- epilogue: exp + masked reductions ----
    int tid_lo[4], tid_hi[4];
#pragma unroll
    for (int mt = 0; mt < 4; mt++) {
        tid_lo[mt] = tid[rowBase + wm * 64 + mt * 16 + g];
        tid_hi[mt] = tid[rowBase + wm * 64 + mt * 16 + g + 8];
    }

#pragma unroll
    for (int mt = 0; mt < 4; mt++) {
        const int r_lo = rowBase + wm * 64 + mt * 16 + g;
        const int r_hi = r_lo + 8;
        float tlo = 0.f, thi = 0.f, plo = 0.f, phi = 0.f;
#pragma unroll
        for (int nt = 0; nt < 8; nt++) {
            const int cA = colBase + wn * 64 + nt * 8 + 2 * tq;
            const int cB = cA + 1;
            int labA, labB;
            if (is_xx) { labA = tid[cA - NY]; labB = tid[cB - NY]; }
            else       { labA = cA & (T_TRACKS - 1); labB = cB & (T_TRACKS - 1); }
            const float e0 = __expf(c[mt][nt][0] * INV_TEMP);  // (r_lo, cA)
            const float e1 = __expf(c[mt][nt][1] * INV_TEMP);  // (r_lo, cB)
            const float e2 = __expf(c[mt][nt][2] * INV_TEMP);  // (r_hi, cA)
            const float e3 = __expf(c[mt][nt][3] * INV_TEMP);  // (r_hi, cB)
            tlo += e0 + e1;
            thi += e2 + e3;
            if (labA == tid_lo[mt]) plo += e0;
            if (labB == tid_lo[mt]) plo += e1;
            if (labA == tid_hi[mt]) phi += e2;
            if (labB == tid_hi[mt]) phi += e3;
            if (is_xx) {
                if (cA - NY == r_lo) g_diag[r_lo] = e0;
                if (cB - NY == r_lo) g_diag[r_lo] = e1;
                if (cA - NY == r_hi) g_diag[r_hi] = e2;
                if (cB - NY == r_hi) g_diag[r_hi] = e3;
            }
        }
        // reduce across the 4 lanes sharing g
#pragma unroll
        for (int off = 1; off < 4; off <<= 1) {
            tlo += __shfl_xor_sync(0xffffffffu, tlo, off);
            thi += __shfl_xor_sync(0xffffffffu, thi, off);
            plo += __shfl_xor_sync(0xffffffffu, plo, off);
            phi += __shfl_xor_sync(0xffffffffu, phi, off);
        }
        if (tq == 0) {
            float* dtot = is_xx ? g_rxx_tot : g_rxy_tot;
            float* dpos = is_xx ? g_rxx_pos : g_rxy_pos;
            atomicAdd(&dtot[r_lo], tlo);
            atomicAdd(&dpos[r_lo], plo);
            atomicAdd(&dtot[r_hi], thi);
            atomicAdd(&dpos[r_hi], phi);
        }
    }
}

// Per-track segment sums + loss; then self-clean accumulators for next replay.
__global__ void finalize_kernel(const int* __restrict__ tid, float* __restrict__ out) {
    __shared__ float num_s[T_TRACKS];
    __shared__ float den_s[T_TRACKS];
    __shared__ int   cnt_s[T_TRACKS];
    __shared__ float lsum[8];
    __shared__ float psum[8];

    const int t = threadIdx.x;
    num_s[t] = 0.f; den_s[t] = 0.f; cnt_s[t] = 0;
    __syncthreads();

    for (int i = t; i < N_ROWS; i += 256) {
        const int tr = tid[i];
        const float num_i = g_rxy_pos[i] + 0.5f * (g_rxx_pos[i] - g_diag[i]);
        const float den_i = (g_rxy_tot[i] - g_rxy_pos[i]) + (g_rxx_tot[i] - g_rxx_pos[i]);
        atomicAdd(&num_s[tr], num_i);
        atomicAdd(&den_s[tr], den_i);
        atomicAdd(&cnt_s[tr], 1);
    }
    __syncthreads();

    // self-clean for next graph replay (reads above are complete)
    for (int i = t; i < N_ROWS; i += 256) {
        g_rxy_tot[i] = 0.f; g_rxy_pos[i] = 0.f;
        g_rxx_tot[i] = 0.f; g_rxx_pos[i] = 0.f;
    }

    float loss = 0.f, pres = 0.f;
    if (cnt_s[t] > 0) {
        const float n = num_s[t];
        const float d = den_s[t];
        loss = -logf(n / (d + n));
        pres = 1.f;
    }
#pragma unroll
    for (int off = 16; off; off >>= 1) {
        loss += __shfl_xor_sync(0xffffffffu, loss, off);
        pres += __shfl_xor_sync(0xffffffffu, pres, off);
    }
    if ((t & 31) == 0) { lsum[t >> 5] = loss; psum[t >> 5] = pres; }
    __syncthreads();
    if (t == 0) {
        float L = 0.f, P = 0.f;
#pragma unroll
        for (int wi = 0; wi < 8; wi++) { L += lsum[wi]; P += psum[wi]; }
        out[0] = L / P;
    }
}

extern "C" void kernel_launch(void* const* d_in, const int* in_sizes, int n_in,
                              void* d_out, int out_size) {
    const float* x   = (const float*)d_in[0];
    const int*   tid = (const int*)d_in[1];
    const float* y   = (const float*)d_in[2];
    float* out = (float*)d_out;

    dim3 grid(N_ROWS / BM, NTOT / BN);  // 16 x 72
    sim_kernel<<<grid, 256>>>(x, tid, y);
    finalize_kernel<<<1, 256>>>(tid, out);
}

// round 7
// speedup vs baseline: 4.6551x; 1.5685x over previous
#include <cuda_runtime.h>
#include <cstdint>

#define N_ROWS   2048
#define DDIM     256
#define T_TRACKS 256
#define NY       16384
#define NTOT     18432
#define BM       128
#define BN       256
#define KC       32
#define NCH      (DDIM / KC)           // 8
#define INV_TEMP (1.0f / 0.3f)

#define A_BYTES  (BM * 128)            // 16384 (128B padded rows, 64B valid)
#define B_BYTES  (BN * 128)            // 32768
#define STAGE    (A_BYTES + B_BYTES)   // 49152
#define SMEM_DYN (2 * STAGE + 1024)

// Scratch accumulators (zero at module load; finalize_kernel self-cleans each replay)
__device__ float g_rxy_tot[N_ROWS];
__device__ float g_rxy_pos[N_ROWS];
__device__ float g_rxx_tot[N_ROWS];
__device__ float g_rxx_pos[N_ROWS];
__device__ float g_diag[N_ROWS];

__device__ __forceinline__ uint32_t smem_u32(const void* p) {
    uint32_t a;
    asm("{ .reg .u64 t; cvta.to.shared.u64 t, %1; cvt.u32.u64 %0, t; }" : "=r"(a) : "l"(p));
    return a;
}
__device__ __forceinline__ unsigned pk(float hi, float lo) {
    unsigned r;
    asm("cvt.rn.bf16x2.f32 %0, %1, %2;" : "=r"(r) : "f"(hi), "f"(lo));
    return r;
}
__device__ __forceinline__ uint32_t swz(uint32_t off) {
    return off ^ ((off >> 3) & 0x70);
}
__device__ __forceinline__ void ldsm4(unsigned* r, uint32_t addr) {
    asm volatile("ldmatrix.sync.aligned.m8n8.x4.shared.b16 {%0,%1,%2,%3}, [%4];"
                 : "=r"(r[0]), "=r"(r[1]), "=r"(r[2]), "=r"(r[3]) : "r"(addr));
}
__device__ __forceinline__ void mma_bf16(float* c, const unsigned* a, const unsigned* b) {
    asm volatile(
        "mma.sync.aligned.m16n8k16.row.col.f32.bf16.bf16.f32 "
        "{%0,%1,%2,%3}, {%4,%5,%6,%7}, {%8,%9}, {%0,%1,%2,%3};"
        : "+f"(c[0]), "+f"(c[1]), "+f"(c[2]), "+f"(c[3])
        : "r"(a[0]), "r"(a[1]), "r"(a[2]), "r"(a[3]), "r"(b[0]), "r"(b[1]));
}

__global__ __launch_bounds__(256, 1) void sim_kernel(const float* __restrict__ x,
                                                     const int*   __restrict__ tid,
                                                     const float* __restrict__ y) {
    extern __shared__ char dynsm[];
    __shared__ int labs[BN];

    const int t    = threadIdx.x;
    const int lane = t & 31;
    const int w    = t >> 5;        // 8 warps
    const int wm   = w >> 2;        // 0..1
    const int wn   = w & 3;         // 0..3
    const int g    = lane >> 2;     // 0..7
    const int tq   = lane & 3;      // 0..3

    const int rowBase = blockIdx.x * BM;
    const int colBase = blockIdx.y * BN;
    const bool is_xx  = (colBase >= NY);
    const float* xptr = x + (size_t)rowBase * DDIM;
    const float* zptr = is_xx ? (x + (size_t)(colBase - NY) * DDIM)
                              : (y + (size_t)colBase * DDIM);

    // 1024B-align dynamic smem
    uint32_t sb  = smem_u32(dynsm);
    uint32_t pad = (1024u - (sb & 1023u)) & 1023u;
    char*    base = dynsm + pad;
    const uint32_t baseAddr = sb + pad;

    {   // labels for this tile's columns
        const int gcol = colBase + t;
        labs[t] = is_xx ? tid[gcol - NY] : (gcol & (T_TRACKS - 1));
    }

    // loader item mapping (A: 2 items/thread, B: 4 items/thread; item = 16B bf16 = 8 f32)
    int arow[2], akq[2], brow[4], bkq[4];
#pragma unroll
    for (int i = 0; i < 2; i++) { const int idx = t + i * 256; arow[i] = idx >> 2; akq[i] = idx & 3; }
#pragma unroll
    for (int i = 0; i < 4; i++) { const int idx = t + i * 256; brow[i] = idx >> 2; bkq[i] = idx & 3; }

    float4 stA[2][2], stB[4][2];
    auto ldg_chunk = [&](int ch) {
#pragma unroll
        for (int i = 0; i < 2; i++) {
            const float* p = xptr + (size_t)arow[i] * DDIM + ch * KC + akq[i] * 8;
            stA[i][0] = *(const float4*)p;
            stA[i][1] = *(const float4*)(p + 4);
        }
#pragma unroll
        for (int i = 0; i < 4; i++) {
            const float* p = zptr + (size_t)brow[i] * DDIM + ch * KC + bkq[i] * 8;
            stB[i][0] = *(const float4*)p;
            stB[i][1] = *(const float4*)(p + 4);
        }
    };
    auto sts_chunk = [&](int stg) {
        char* sA = base + stg * STAGE;
        char* sB = sA + A_BYTES;
#pragma unroll
        for (int i = 0; i < 2; i++) {
            uint4 v;
            v.x = pk(stA[i][0].y, stA[i][0].x); v.y = pk(stA[i][0].w, stA[i][0].z);
            v.z = pk(stA[i][1].y, stA[i][1].x); v.w = pk(stA[i][1].w, stA[i][1].z);
            *(uint4*)(sA + swz((uint32_t)(arow[i] * 128 + akq[i] * 16))) = v;
        }
#pragma unroll
        for (int i = 0; i < 4; i++) {
            uint4 v;
            v.x = pk(stB[i][0].y, stB[i][0].x); v.y = pk(stB[i][0].w, stB[i][0].z);
            v.z = pk(stB[i][1].y, stB[i][1].x); v.w = pk(stB[i][1].w, stB[i][1].z);
            *(uint4*)(sB + swz((uint32_t)(brow[i] * 128 + bkq[i] * 16))) = v;
        }
    };

    // ldmatrix per-lane offsets — swizzle applied to the FULL offset incl. k-half
    // (swizzle is NOT additive in the k byte-offset; this was the R4/R5 bug)
    uint32_t aoff[4][2], boff[4][2];
    {
        const int rA = lane & 15;
        const int kA = (lane >> 4) * 16;
#pragma unroll
        for (int mt = 0; mt < 4; mt++)
#pragma unroll
            for (int s = 0; s < 2; s++)
                aoff[mt][s] = swz((uint32_t)((wm * 64 + mt * 16 + rA) * 128 + kA + s * 32));
        const int rB = (lane & 7) + (lane >> 4) * 8;
        const int kB = ((lane >> 3) & 1) * 16;
#pragma unroll
        for (int p = 0; p < 4; p++)
#pragma unroll
            for (int s = 0; s < 2; s++)
                boff[p][s] = swz((uint32_t)((wn * 64 + p * 16 + rB) * 128 + kB + s * 32));
    }

    float c[4][8][4];
#pragma unroll
    for (int mt = 0; mt < 4; mt++)
#pragma unroll
        for (int nt = 0; nt < 8; nt++)
#pragma unroll
            for (int q = 0; q < 4; q++) c[mt][nt][q] = 0.f;

    ldg_chunk(0);
    sts_chunk(0);
    __syncthreads();

    for (int ch = 0; ch < NCH; ch++) {
        if (ch + 1 < NCH) ldg_chunk(ch + 1);

        const uint32_t aAdr = baseAddr + (ch & 1) * STAGE;
        const uint32_t bAdr = aAdr + A_BYTES;
#pragma unroll
        for (int s = 0; s < 2; s++) {
            unsigned af[4][4];
#pragma unroll
            for (int mt = 0; mt < 4; mt++) ldsm4(af[mt], aAdr + aoff[mt][s]);
#pragma unroll
            for (int p = 0; p < 4; p++) {
                unsigned bf[4];
                ldsm4(bf, bAdr + boff[p][s]);
#pragma unroll
                for (int mt = 0; mt < 4; mt++) {
                    mma_bf16(c[mt][2 * p + 0], af[mt], bf + 0);
                    mma_bf16(c[mt][2 * p + 1], af[mt], bf + 2);
                }
            }
        }

        if (ch + 1 < NCH) sts_chunk((ch + 1) & 1);
        __syncthreads();
    }

    // ---- epilogue: exp + masked reductions ----
    int tid_lo[4], tid_hi[4];
#pragma unroll
    for (int mt = 0; mt < 4; mt++) {
        tid_lo[mt] = tid[rowBase + wm * 64 + mt * 16 + g];
        tid_hi[mt] = tid[rowBase + wm * 64 + mt * 16 + g + 8];
    }

#pragma unroll
    for (int mt = 0; mt < 4; mt++) {
        const int r_lo = rowBase + wm * 64 + mt * 16 + g;
        const int r_hi = r_lo + 8;
        float tlo = 0.f, thi = 0.f, plo = 0.f, phi = 0.f;
#pragma unroll
        for (int nt = 0; nt < 8; nt++) {
            const int clA = wn * 64 + nt * 8 + 2 * tq;
            const int labA = labs[clA], labB = labs[clA + 1];
            const float e0 = __expf(c[mt][nt][0] * INV_TEMP);
            const float e1 = __expf(c[mt][nt][1] * INV_TEMP);
            const float e2 = __expf(c[mt][nt][2] * INV_TEMP);
            const float e3 = __expf(c[mt][nt][3] * INV_TEMP);
            tlo += e0 + e1;
            thi += e2 + e3;
            if (labA == tid_lo[mt]) plo += e0;
            if (labB == tid_lo[mt]) plo += e1;
            if (labA == tid_hi[mt]) phi += e2;
            if (labB == tid_hi[mt]) phi += e3;
            if (is_xx) {
                const int gcA = colBase - NY + clA;
                if (gcA == r_lo) g_diag[r_lo] = e0;
                if (gcA + 1 == r_lo) g_diag[r_lo] = e1;
                if (gcA == r_hi) g_diag[r_hi] = e2;
                if (gcA + 1 == r_hi) g_diag[r_hi] = e3;
            }
        }
#pragma unroll
        for (int off = 1; off < 4; off <<= 1) {
            tlo += __shfl_xor_sync(0xffffffffu, tlo, off);
            thi += __shfl_xor_sync(0xffffffffu, thi, off);
            plo += __shfl_xor_sync(0xffffffffu, plo, off);
            phi += __shfl_xor_sync(0xffffffffu, phi, off);
        }
        if (tq == 0) {
            float* dt = is_xx ? g_rxx_tot : g_rxy_tot;
            float* dp = is_xx ? g_rxx_pos : g_rxy_pos;
            atomicAdd(&dt[r_lo], tlo);
            atomicAdd(&dp[r_lo], plo);
            atomicAdd(&dt[r_hi], thi);
            atomicAdd(&dp[r_hi], phi);
        }
    }
}

// Per-track segment sums + loss; self-cleans accumulators for next graph replay.
__global__ void finalize_kernel(const int* __restrict__ tid, float* __restrict__ out) {
    __shared__ float num_s[T_TRACKS];
    __shared__ float den_s[T_TRACKS];
    __shared__ int   cnt_s[T_TRACKS];
    __shared__ float lsum[8];
    __shared__ float psum[8];

    const int t = threadIdx.x;
    num_s[t] = 0.f; den_s[t] = 0.f; cnt_s[t] = 0;
    __syncthreads();

#pragma unroll
    for (int i = t; i < N_ROWS; i += 256) {
        const int tr = tid[i];
        const float num_i = g_rxy_pos[i] + 0.5f * (g_rxx_pos[i] - g_diag[i]);
        const float den_i = (g_rxy_tot[i] - g_rxy_pos[i]) + (g_rxx_tot[i] - g_rxx_pos[i]);
        atomicAdd(&num_s[tr], num_i);
        atomicAdd(&den_s[tr], den_i);
        atomicAdd(&cnt_s[tr], 1);
    }
    __syncthreads();

    // self-clean for next graph replay (reads above are complete)
#pragma unroll
    for (int i = t; i < N_ROWS; i += 256) {
        g_rxy_tot[i] = 0.f; g_rxy_pos[i] = 0.f;
        g_rxx_tot[i] = 0.f; g_rxx_pos[i] = 0.f;
    }

    float loss = 0.f, pres = 0.f;
    if (cnt_s[t] > 0) {
        const float n = num_s[t];
        const float d = den_s[t];
        loss = -logf(n / (d + n));
        pres = 1.f;
    }
#pragma unroll
    for (int off = 16; off; off >>= 1) {
        loss += __shfl_xor_sync(0xffffffffu, loss, off);
        pres += __shfl_xor_sync(0xffffffffu, pres, off);
    }
    if ((t & 31) == 0) { lsum[t >> 5] = loss; psum[t >> 5] = pres; }
    __syncthreads();
    if (t == 0) {
        float L = 0.f, P = 0.f;
#pragma unroll
        for (int wi = 0; wi < 8; wi++) { L += lsum[wi]; P += psum[wi]; }
        out[0] = L / P;
    }
}

extern "C" void kernel_launch(void* const* d_in, const int* in_sizes, int n_in,
                              void* d_out, int out_size) {
    const float* x   = (const float*)d_in[0];
    const int*   tid = (const int*)d_in[1];
    const float* y   = (const float*)d_in[2];
    float* out = (float*)d_out;

    cudaFuncSetAttribute(sim_kernel, cudaFuncAttributeMaxDynamicSharedMemorySize, SMEM_DYN);
    dim3 grid(N_ROWS / BM, NTOT / BN);   // 16 x 72
    sim_kernel<<<grid, 256, SMEM_DYN>>>(x, tid, y);
    finalize_kernel<<<1, 256>>>(tid, out);
}

// round 10
// speedup vs baseline: 8.7634x; 1.8825x over previous
#include <cuda_runtime.h>
#include <cstdint>

#define N_ROWS   2048
#define DDIM     256
#define T_TRACKS 256
#define NY       16384
#define NTOT     18432
#define BM       128
#define BN       256
#define KC       64
#define NCH      (DDIM / KC)           // 4
#define NSTAGE   3
#define INV_TEMP (1.0f / 0.3f)

#define A_BYTES  (BM * 128)            // 16384 (128B = 64 bf16 per row-chunk)
#define B_BYTES  (BN * 128)            // 32768
#define STAGE    (A_BYTES + B_BYTES)   // 49152
#define SMEM_DYN (NSTAGE * STAGE + 1024)

// Scratch (zero at module load; finalize self-cleans each replay)
__device__ float    g_rxy_tot[N_ROWS];
__device__ float    g_rxy_pos[N_ROWS];
__device__ float    g_rxx_tot[N_ROWS];
__device__ float    g_rxx_pos[N_ROWS];
__device__ float    g_diag[N_ROWS];
// bf16 copies of inputs (bf16x2 packed, k-contiguous), rebuilt every call
__device__ unsigned g_xb[N_ROWS * DDIM / 2];    // 2048*128 u32
__device__ unsigned g_yb[NY * DDIM / 2];        // 16384*128 u32

__device__ __forceinline__ uint32_t smem_u32(const void* p) {
    uint32_t a;
    asm("{ .reg .u64 t; cvta.to.shared.u64 t, %1; cvt.u32.u64 %0, t; }" : "=r"(a) : "l"(p));
    return a;
}
__device__ __forceinline__ unsigned pk(float hi, float lo) {
    unsigned r;
    asm("cvt.rn.bf16x2.f32 %0, %1, %2;" : "=r"(r) : "f"(hi), "f"(lo));
    return r;
}
__device__ __forceinline__ uint32_t swz(uint32_t off) {
    return off ^ ((off >> 3) & 0x70);
}
__device__ __forceinline__ void cpasync16(uint32_t dst, const void* src) {
    asm volatile("cp.async.ca.shared.global [%0], [%1], 16;" :: "r"(dst), "l"(src));
}
#define CP_COMMIT() asm volatile("cp.async.commit_group;" ::: "memory")
#define CP_WAIT(N)  asm volatile("cp.async.wait_group %0;" :: "n"(N) : "memory")
__device__ __forceinline__ void ldsm4(unsigned* r, uint32_t addr) {
    asm volatile("ldmatrix.sync.aligned.m8n8.x4.shared.b16 {%0,%1,%2,%3}, [%4];"
                 : "=r"(r[0]), "=r"(r[1]), "=r"(r[2]), "=r"(r[3]) : "r"(addr));
}
__device__ __forceinline__ void mma_bf16(float* c, const unsigned* a, const unsigned* b) {
    asm volatile(
        "mma.sync.aligned.m16n8k16.row.col.f32.bf16.bf16.f32 "
        "{%0,%1,%2,%3}, {%4,%5,%6,%7}, {%8,%9}, {%0,%1,%2,%3};"
        : "+f"(c[0]), "+f"(c[1]), "+f"(c[2]), "+f"(c[3])
        : "r"(a[0]), "r"(a[1]), "r"(a[2]), "r"(a[3]), "r"(b[0]), "r"(b[1]));
}

// fp32 -> bf16x2 pre-conversion (same work every call; deterministic)
__global__ void conv_kernel(const float* __restrict__ x, const float* __restrict__ y) {
    const int NXP = N_ROWS * DDIM / 2;
    const int NYP = NY * DDIM / 2;
    for (int i = blockIdx.x * blockDim.x + threadIdx.x; i < NXP + NYP;
         i += gridDim.x * blockDim.x) {
        if (i < NXP) {
            float2 v = ((const float2*)x)[i];
            g_xb[i] = pk(v.y, v.x);
        } else {
            float2 v = ((const float2*)y)[i - NXP];
            g_yb[i - NXP] = pk(v.y, v.x);
        }
    }
}

__global__ void nop_kernel() {}

__global__ __launch_bounds__(256, 1) void sim_kernel(const int* __restrict__ tid) {
    extern __shared__ char dynsm[];
    __shared__ int labs[BN];

    const int t    = threadIdx.x;
    const int lane = t & 31;
    const int w    = t >> 5;        // 8 warps
    const int wm   = w >> 2;        // 0..1
    const int wn   = w & 3;         // 0..3
    const int g    = lane >> 2;     // 0..7
    const int tq   = lane & 3;      // 0..3

    const int rowBase = blockIdx.x * BM;
    const int colBase = blockIdx.y * BN;
    const bool is_xx  = (colBase >= NY);
    const char* asrc = (const char*)g_xb + (size_t)rowBase * 512;   // 512B per row
    const char* bsrc = is_xx ? ((const char*)g_xb + (size_t)(colBase - NY) * 512)
                             : ((const char*)g_yb + (size_t)colBase * 512);

    uint32_t sb  = smem_u32(dynsm);
    uint32_t pad = (1024u - (sb & 1023u)) & 1023u;
    const uint32_t baseAddr = sb + pad;

    {   // labels for this tile's columns
        const int gcol = colBase + t;
        labs[t] = is_xx ? tid[gcol - NY] : (gcol & (T_TRACKS - 1));
    }

    // cp.async granule mapping: A = 1024 granules (128 rows x 8), B = 2048
    int arow_[4], akq_[4], brow_[8], bkq_[8];
    uint32_t adst_[4], bdst_[8];
#pragma unroll
    for (int i = 0; i < 4; i++) {
        const int idx = t + i * 256;
        arow_[i] = idx >> 3; akq_[i] = idx & 7;
        adst_[i] = swz((uint32_t)(arow_[i] * 128 + akq_[i] * 16));
    }
#pragma unroll
    for (int i = 0; i < 8; i++) {
        const int idx = t + i * 256;
        brow_[i] = idx >> 3; bkq_[i] = idx & 7;
        bdst_[i] = swz((uint32_t)(brow_[i] * 128 + bkq_[i] * 16));
    }

    auto issue_chunk = [&](int ch, int stg) {
        const uint32_t sA = baseAddr + stg * STAGE;
        const uint32_t sB = sA + A_BYTES;
#pragma unroll
        for (int i = 0; i < 4; i++)
            cpasync16(sA + adst_[i], asrc + (size_t)arow_[i] * 512 + ch * 128 + akq_[i] * 16);
#pragma unroll
        for (int i = 0; i < 8; i++)
            cpasync16(sB + bdst_[i], bsrc + (size_t)brow_[i] * 512 + ch * 128 + bkq_[i] * 16);
        CP_COMMIT();
    };

    // ldmatrix base offsets (s=0); k-step s applied as XOR (s<<5) — exact under SW128
    uint32_t aoffB[4], boffB[4];
    {
        const int rA = lane & 15;
        const int kA = (lane >> 4) * 16;
#pragma unroll
        for (int mt = 0; mt < 4; mt++)
            aoffB[mt] = swz((uint32_t)((wm * 64 + mt * 16 + rA) * 128 + kA));
        const int rB = (lane & 7) + (lane >> 4) * 8;
        const int kB = ((lane >> 3) & 1) * 16;
#pragma unroll
        for (int p = 0; p < 4; p++)
            boffB[p] = swz((uint32_t)((wn * 64 + p * 16 + rB) * 128 + kB));
    }

    float c[4][8][4];
#pragma unroll
    for (int mt = 0; mt < 4; mt++)
#pragma unroll
        for (int nt = 0; nt < 8; nt++)
#pragma unroll
            for (int q = 0; q < 4; q++) c[mt][nt][q] = 0.f;

    issue_chunk(0, 0);
    issue_chunk(1, 1);

#pragma unroll
    for (int ch = 0; ch < NCH; ch++) {
        if (ch < NCH - 1) CP_WAIT(1); else CP_WAIT(0);
        __syncthreads();
        if (ch + 2 < NCH) issue_chunk(ch + 2, (ch + 2) % NSTAGE);

        const uint32_t aAdr = baseAddr + (ch % NSTAGE) * STAGE;
        const uint32_t bAdr = aAdr + A_BYTES;
#pragma unroll
        for (int s = 0; s < 4; s++) {
            const uint32_t sx = (uint32_t)(s << 5);
            unsigned af[4][4];
#pragma unroll
            for (int mt = 0; mt < 4; mt++) ldsm4(af[mt], aAdr + (aoffB[mt] ^ sx));
#pragma unroll
            for (int p = 0; p < 4; p++) {
                unsigned bf[4];
                ldsm4(bf, bAdr + (boffB[p] ^ sx));
#pragma unroll
                for (int mt = 0; mt < 4; mt++) {
                    mma_bf16(c[mt][2 * p + 0], af[mt], bf + 0);
                    mma_bf16(c[mt][2 * p + 1], af[mt], bf + 2);
                }
            }
        }
    }

    // ---- epilogue: exp + masked reductions ----
    int tid_lo[4], tid_hi[4];
#pragma unroll
    for (int mt = 0; mt < 4; mt++) {
        tid_lo[mt] = tid[rowBase + wm * 64 + mt * 16 + g];
        tid_hi[mt] = tid[rowBase + wm * 64 + mt * 16 + g + 8];
    }

#pragma unroll
    for (int mt = 0; mt < 4; mt++) {
        const int r_lo = rowBase + wm * 64 + mt * 16 + g;
        const int r_hi = r_lo + 8;
        float tlo = 0.f, thi = 0.f, plo = 0.f, phi = 0.f;
#pragma unroll
        for (int nt = 0; nt < 8; nt++) {
            const int clA = wn * 64 + nt * 8 + 2 * tq;
            const int labA = labs[clA], labB = labs[clA + 1];
            const float e0 = __expf(c[mt][nt][0] * INV_TEMP);
            const float e1 = __expf(c[mt][nt][1] * INV_TEMP);
            const float e2 = __expf(c[mt][nt][2] * INV_TEMP);
            const float e3 = __expf(c[mt][nt][3] * INV_TEMP);
            tlo += e0 + e1;
            thi += e2 + e3;
            if (labA == tid_lo[mt]) plo += e0;
            if (labB == tid_lo[mt]) plo += e1;
            if (labA == tid_hi[mt]) phi += e2;
            if (labB == tid_hi[mt]) phi += e3;
            if (is_xx) {
                const int gcA = colBase - NY + clA;
                if (gcA == r_lo) g_diag[r_lo] = e0;
                if (gcA + 1 == r_lo) g_diag[r_lo] = e1;
                if (gcA == r_hi) g_diag[r_hi] = e2;
                if (gcA + 1 == r_hi) g_diag[r_hi] = e3;
            }
        }
#pragma unroll
        for (int off = 1; off < 4; off <<= 1) {
            tlo += __shfl_xor_sync(0xffffffffu, tlo, off);
            thi += __shfl_xor_sync(0xffffffffu, thi, off);
            plo += __shfl_xor_sync(0xffffffffu, plo, off);
            phi += __shfl_xor_sync(0xffffffffu, phi, off);
        }
        if (tq == 0) {
            float* dt = is_xx ? g_rxx_tot : g_rxy_tot;
            float* dp = is_xx ? g_rxx_pos : g_rxy_pos;
            atomicAdd(&dt[r_lo], tlo);
            atomicAdd(&dp[r_lo], plo);
            atomicAdd(&dt[r_hi], thi);
            atomicAdd(&dp[r_hi], phi);
        }
    }
}

// Per-track segment sums + loss; self-cleans accumulators for next graph replay.
__global__ void finalize_kernel(const int* __restrict__ tid, float* __restrict__ out) {
    __shared__ float num_s[T_TRACKS];
    __shared__ float den_s[T_TRACKS];
    __shared__ int   cnt_s[T_TRACKS];
    __shared__ float lsum[32];
    __shared__ float psum[32];

    const int t = threadIdx.x;     // 1024 threads
    if (t < T_TRACKS) { num_s[t] = 0.f; den_s[t] = 0.f; cnt_s[t] = 0; }
    __syncthreads();

#pragma unroll
    for (int i = t; i < N_ROWS; i += 1024) {
        const int tr = tid[i];
        const float num_i = g_rxy_pos[i] + 0.5f * (g_rxx_pos[i] - g_diag[i]);
        const float den_i = (g_rxy_tot[i] - g_rxy_pos[i]) + (g_rxx_tot[i] - g_rxx_pos[i]);
        atomicAdd(&num_s[tr], num_i);
        atomicAdd(&den_s[tr], den_i);
        atomicAdd(&cnt_s[tr], 1);
    }
    __syncthreads();

    // self-clean for next graph replay
#pragma unroll
    for (int i = t; i < N_ROWS; i += 1024) {
        g_rxy_tot[i] = 0.f; g_rxy_pos[i] = 0.f;
        g_rxx_tot[i] = 0.f; g_rxx_pos[i] = 0.f;
    }

    float loss = 0.f, pres = 0.f;
    if (t < T_TRACKS && cnt_s[t] > 0) {
        const float n = num_s[t];
        const float d = den_s[t];
        loss = -logf(n / (d + n));
        pres = 1.f;
    }
#pragma unroll
    for (int off = 16; off; off >>= 1) {
        loss += __shfl_xor_sync(0xffffffffu, loss, off);
        pres += __shfl_xor_sync(0xffffffffu, pres, off);
    }
    if ((t & 31) == 0) { lsum[t >> 5] = loss; psum[t >> 5] = pres; }
    __syncthreads();
    if (t == 0) {
        float L = 0.f, P = 0.f;
#pragma unroll
        for (int wi = 0; wi < 32; wi++) { L += lsum[wi]; P += psum[wi]; }
        out[0] = L / P;
    }
}

extern "C" void kernel_launch(void* const* d_in, const int* in_sizes, int n_in,
                              void* d_out, int out_size) {
    const float* x   = (const float*)d_in[0];
    const int*   tid = (const int*)d_in[1];
    const float* y   = (const float*)d_in[2];
    float* out = (float*)d_out;

    cudaFuncSetAttribute(sim_kernel, cudaFuncAttributeMaxDynamicSharedMemorySize, SMEM_DYN);
    conv_kernel<<<592, 256>>>(x, y);   // 4 full waves on 148 SMs
    dim3 grid(N_ROWS / BM, NTOT / BN); // 16 x 72
    sim_kernel<<<grid, 256, SMEM_DYN>>>(tid);
    finalize_kernel<<<1, 1024>>>(tid, out);
    nop_kernel<<<1, 32>>>();   // pads to 4 launches/call so ncu (-s 5) profiles sim_kernel
}

// round 12
// speedup vs baseline: 8.7928x; 1.0034x over previous
#include <cuda_runtime.h>
#include <cstdint>

#define N_ROWS   2048
#define DDIM     256
#define T_TRACKS 256
#define NY       16384
#define NTOT     18432
#define BM       128
#define BN       128
#define KC       64
#define NCH      (DDIM / KC)           // 4
#define NSTAGE   3
#define INV_TEMP (1.0f / 0.3f)

#define A_BYTES  (BM * 128)            // 16384
#define B_BYTES  (BN * 128)            // 16384
#define STAGE    (A_BYTES + B_BYTES)   // 32768
#define SMEM_DYN (NSTAGE * STAGE + 1024)   // 99328 -> 2 CTAs/SM

// Scratch (zero at module load; finalize self-cleans each replay)
__device__ float    g_rxy_tot[N_ROWS];
__device__ float    g_rxy_pos[N_ROWS];
__device__ float    g_rxx_tot[N_ROWS];
__device__ float    g_rxx_pos[N_ROWS];
__device__ float    g_diag[N_ROWS];
// bf16 copies of inputs (bf16x2 packed, k-contiguous), rebuilt every call
__device__ unsigned g_xb[N_ROWS * DDIM / 2];
__device__ unsigned g_yb[NY * DDIM / 2];

__device__ __forceinline__ uint32_t smem_u32(const void* p) {
    uint32_t a;
    asm("{ .reg .u64 t; cvta.to.shared.u64 t, %1; cvt.u32.u64 %0, t; }" : "=r"(a) : "l"(p));
    return a;
}
__device__ __forceinline__ unsigned pk(float hi, float lo) {
    unsigned r;
    asm("cvt.rn.bf16x2.f32 %0, %1, %2;" : "=r"(r) : "f"(hi), "f"(lo));
    return r;
}
__device__ __forceinline__ uint32_t swz(uint32_t off) {
    return off ^ ((off >> 3) & 0x70);
}
__device__ __forceinline__ void cpasync16(uint32_t dst, const void* src) {
    asm volatile("cp.async.ca.shared.global [%0], [%1], 16;" :: "r"(dst), "l"(src));
}
#define CP_COMMIT() asm volatile("cp.async.commit_group;" ::: "memory")
#define CP_WAIT(N)  asm volatile("cp.async.wait_group %0;" :: "n"(N) : "memory")
__device__ __forceinline__ void ldsm4(unsigned* r, uint32_t addr) {
    asm volatile("ldmatrix.sync.aligned.m8n8.x4.shared.b16 {%0,%1,%2,%3}, [%4];"
                 : "=r"(r[0]), "=r"(r[1]), "=r"(r[2]), "=r"(r[3]) : "r"(addr));
}
__device__ __forceinline__ void mma_bf16(float* c, const unsigned* a, const unsigned* b) {
    asm volatile(
        "mma.sync.aligned.m16n8k16.row.col.f32.bf16.bf16.f32 "
        "{%0,%1,%2,%3}, {%4,%5,%6,%7}, {%8,%9}, {%0,%1,%2,%3};"
        : "+f"(c[0]), "+f"(c[1]), "+f"(c[2]), "+f"(c[3])
        : "r"(a[0]), "r"(a[1]), "r"(a[2]), "r"(a[3]), "r"(b[0]), "r"(b[1]));
}

// fp32 -> bf16x2 pre-conversion (same work every call; deterministic)
__global__ void conv_kernel(const float* __restrict__ x, const float* __restrict__ y) {
    const int NXP = N_ROWS * DDIM / 2;
    const int NYP = NY * DDIM / 2;
    for (int i = blockIdx.x * blockDim.x + threadIdx.x; i < NXP + NYP;
         i += gridDim.x * blockDim.x) {
        if (i < NXP) {
            float2 v = ((const float2*)x)[i];
            g_xb[i] = pk(v.y, v.x);
        } else {
            float2 v = ((const float2*)y)[i - NXP];
            g_yb[i - NXP] = pk(v.y, v.x);
        }
    }
}

__global__ __launch_bounds__(256, 2) void sim_kernel(const int* __restrict__ tid) {
    extern __shared__ char dynsm[];
    __shared__ int labs[BN];

    const int t    = threadIdx.x;
    const int lane = t & 31;
    const int w    = t >> 5;        // 8 warps
    const int wm   = w >> 2;        // 0..1  (64 rows each)
    const int wn   = w & 3;         // 0..3  (32 cols each)
    const int g    = lane >> 2;     // 0..7
    const int tq   = lane & 3;      // 0..3

    const int rowBase = blockIdx.x * BM;
    const int colBase = blockIdx.y * BN;
    const bool is_xx  = (colBase >= NY);
    const char* asrc = (const char*)g_xb + (size_t)rowBase * 512;   // 512B per row
    const char* bsrc = is_xx ? ((const char*)g_xb + (size_t)(colBase - NY) * 512)
                             : ((const char*)g_yb + (size_t)colBase * 512);

    uint32_t sb  = smem_u32(dynsm);
    uint32_t pad = (1024u - (sb & 1023u)) & 1023u;
    const uint32_t baseAddr = sb + pad;

    if (t < BN) {   // labels for this tile's columns
        const int gcol = colBase + t;
        labs[t] = is_xx ? tid[gcol - NY] : (gcol & (T_TRACKS - 1));
    }

    // cp.async granule mapping: A and B each 1024 granules -> 4 per thread
    int arow_[4], akq_[4], brow_[4], bkq_[4];
    uint32_t adst_[4], bdst_[4];
#pragma unroll
    for (int i = 0; i < 4; i++) {
        const int idx = t + i * 256;
        arow_[i] = idx >> 3; akq_[i] = idx & 7;
        adst_[i] = swz((uint32_t)(arow_[i] * 128 + akq_[i] * 16));
        brow_[i] = arow_[i]; bkq_[i] = akq_[i];
        bdst_[i] = adst_[i];
    }

    auto issue_chunk = [&](int ch, int stg) {
        const uint32_t sA = baseAddr + stg * STAGE;
        const uint32_t sB = sA + A_BYTES;
#pragma unroll
        for (int i = 0; i < 4; i++)
            cpasync16(sA + adst_[i], asrc + (size_t)arow_[i] * 512 + ch * 128 + akq_[i] * 16);
#pragma unroll
        for (int i = 0; i < 4; i++)
            cpasync16(sB + bdst_[i], bsrc + (size_t)brow_[i] * 512 + ch * 128 + bkq_[i] * 16);
        CP_COMMIT();
    };

    // ldmatrix base offsets (s=0); k-step applied as XOR (s<<5) — exact under SW128
    uint32_t aoffB[4], boffB[2];
    {
        const int rA = lane & 15;
        const int kA = (lane >> 4) * 16;
#pragma unroll
        for (int mt = 0; mt < 4; mt++)
            aoffB[mt] = swz((uint32_t)((wm * 64 + mt * 16 + rA) * 128 + kA));
        const int rB = (lane & 7) + (lane >> 4) * 8;
        const int kB = ((lane >> 3) & 1) * 16;
#pragma unroll
        for (int p = 0; p < 2; p++)
            boffB[p] = swz((uint32_t)((wn * 32 + p * 16 + rB) * 128 + kB));
    }

    float c[4][4][4];
#pragma unroll
    for (int mt = 0; mt < 4; mt++)
#pragma unroll
        for (int nt = 0; nt < 4; nt++)
#pragma unroll
            for (int q = 0; q < 4; q++) c[mt][nt][q] = 0.f;

    issue_chunk(0, 0);
    issue_chunk(1, 1);

#pragma unroll
    for (int ch = 0; ch < NCH; ch++) {
        if (ch < NCH - 1) CP_WAIT(1); else CP_WAIT(0);
        __syncthreads();
        if (ch + 2 < NCH) issue_chunk(ch + 2, (ch + 2) % NSTAGE);

        const uint32_t aAdr = baseAddr + (ch % NSTAGE) * STAGE;
        const uint32_t bAdr = aAdr + A_BYTES;
#pragma unroll
        for (int s = 0; s < 4; s++) {
            const uint32_t sx = (uint32_t)(s << 5);
            unsigned af[4][4];
#pragma unroll
            for (int mt = 0; mt < 4; mt++) ldsm4(af[mt], aAdr + (aoffB[mt] ^ sx));
#pragma unroll
            for (int p = 0; p < 2; p++) {
                unsigned bf[4];
                ldsm4(bf, bAdr + (boffB[p] ^ sx));
#pragma unroll
                for (int mt = 0; mt < 4; mt++) {
                    mma_bf16(c[mt][2 * p + 0], af[mt], bf + 0);
                    mma_bf16(c[mt][2 * p + 1], af[mt], bf + 2);
                }
            }
        }
    }

    // ---- epilogue: exp + masked reductions ----
    int tid_lo[4], tid_hi[4];
#pragma unroll
    for (int mt = 0; mt < 4; mt++) {
        tid_lo[mt] = tid[rowBase + wm * 64 + mt * 16 + g];
        tid_hi[mt] = tid[rowBase + wm * 64 + mt * 16 + g + 8];
    }

#pragma unroll
    for (int mt = 0; mt < 4; mt++) {
        const int r_lo = rowBase + wm * 64 + mt * 16 + g;
        const int r_hi = r_lo + 8;
        float tlo = 0.f, thi = 0.f, plo = 0.f, phi = 0.f;
#pragma unroll
        for (int nt = 0; nt < 4; nt++) {
            const int clA = wn * 32 + nt * 8 + 2 * tq;
            const int labA = labs[clA], labB = labs[clA + 1];
            const float e0 = __expf(c[mt][nt][0] * INV_TEMP);
            const float e1 = __expf(c[mt][nt][1] * INV_TEMP);
            const float e2 = __expf(c[mt][nt][2] * INV_TEMP);
            const float e3 = __expf(c[mt][nt][3] * INV_TEMP);
            tlo += e0 + e1;
            thi += e2 + e3;
            if (labA == tid_lo[mt]) plo += e0;
            if (labB == tid_lo[mt]) plo += e1;
            if (labA == tid_hi[mt]) phi += e2;
            if (labB == tid_hi[mt]) phi += e3;
            if (is_xx) {
                const int gcA = colBase - NY + clA;
                if (gcA == r_lo) g_diag[r_lo] = e0;
                if (gcA + 1 == r_lo) g_diag[r_lo] = e1;
                if (gcA == r_hi) g_diag[r_hi] = e2;
                if (gcA + 1 == r_hi) g_diag[r_hi] = e3;
            }
        }
#pragma unroll
        for (int off = 1; off < 4; off <<= 1) {
            tlo += __shfl_xor_sync(0xffffffffu, tlo, off);
            thi += __shfl_xor_sync(0xffffffffu, thi, off);
            plo += __shfl_xor_sync(0xffffffffu, plo, off);
            phi += __shfl_xor_sync(0xffffffffu, phi, off);
        }
        if (tq == 0) {
            float* dt = is_xx ? g_rxx_tot : g_rxy_tot;
            float* dp = is_xx ? g_rxx_pos : g_rxy_pos;
            atomicAdd(&dt[r_lo], tlo);
            atomicAdd(&dp[r_lo], plo);
            atomicAdd(&dt[r_hi], thi);
            atomicAdd(&dp[r_hi], phi);
        }
    }
}

// Per-track segment sums + loss; self-cleans accumulators for next graph replay.
__global__ void finalize_kernel(const int* __restrict__ tid, float* __restrict__ out) {
    __shared__ float num_s[T_TRACKS];
    __shared__ float den_s[T_TRACKS];
    __shared__ int   cnt_s[T_TRACKS];
    __shared__ float lsum[32];
    __shared__ float psum[32];

    const int t = threadIdx.x;     // 1024 threads
    if (t < T_TRACKS) { num_s[t] = 0.f; den_s[t] = 0.f; cnt_s[t] = 0; }
    __syncthreads();

#pragma unroll
    for (int i = t; i < N_ROWS; i += 1024) {
        const int tr = tid[i];
        const float num_i = g_rxy_pos[i] + 0.5f * (g_rxx_pos[i] - g_diag[i]);
        const float den_i = (g_rxy_tot[i] - g_rxy_pos[i]) + (g_rxx_tot[i] - g_rxx_pos[i]);
        atomicAdd(&num_s[tr], num_i);
        atomicAdd(&den_s[tr], den_i);
        atomicAdd(&cnt_s[tr], 1);
    }
    __syncthreads();

    // self-clean for next graph replay
#pragma unroll
    for (int i = t; i < N_ROWS; i += 1024) {
        g_rxy_tot[i] = 0.f; g_rxy_pos[i] = 0.f;
        g_rxx_tot[i] = 0.f; g_rxx_pos[i] = 0.f;
    }

    float loss = 0.f, pres = 0.f;
    if (t < T_TRACKS && cnt_s[t] > 0) {
        const float n = num_s[t];
        const float d = den_s[t];
        loss = -logf(n / (d + n));
        pres = 1.f;
    }
#pragma unroll
    for (int off = 16; off; off >>= 1) {
        loss += __shfl_xor_sync(0xffffffffu, loss, off);
        pres += __shfl_xor_sync(0xffffffffu, pres, off);
    }
    if ((t & 31) == 0) { lsum[t >> 5] = loss; psum[t >> 5] = pres; }
    __syncthreads();
    if (t == 0) {
        float L = 0.f, P = 0.f;
#pragma unroll
        for (int wi = 0; wi < 32; wi++) { L += lsum[wi]; P += psum[wi]; }
        out[0] = L / P;
    }
}

extern "C" void kernel_launch(void* const* d_in, const int* in_sizes, int n_in,
                              void* d_out, int out_size) {
    const float* x   = (const float*)d_in[0];
    const int*   tid = (const int*)d_in[1];
    const float* y   = (const float*)d_in[2];
    float* out = (float*)d_out;

    cudaFuncSetAttribute(sim_kernel, cudaFuncAttributeMaxDynamicSharedMemorySize, SMEM_DYN);
    conv_kernel<<<592, 256>>>(x, y);
    dim3 grid(N_ROWS / BM, NTOT / BN);   // 16 x 144
    sim_kernel<<<grid, 256, SMEM_DYN>>>(tid);
    finalize_kernel<<<1, 1024>>>(tid, out);
}